// round 2
// baseline (speedup 1.0000x reference)
#include <cuda_runtime.h>
#include <math.h>
#include <stdint.h>

// ---------------------------------------------------------------------------
// COR_Critic: fused critic MLP
//   sa  = concat(state[B,24], action[B,8])          -> [B,32]
//   X1  = tanh(sa @ A1 + b1) * gate1                -> [B,1024]   (ripple 1)
//   X2  = tanh(X1 @ A2 + b2) * gate2                -> [B,1024]   (ripple 2)
//   H1  = relu(LN(X2 @ Wq1 + bq1))                  -> [B,256]
//   H2  = relu(LN(H1 @ Wq2 + bq2))                  -> [B,128]
//   out = H2 @ Wq3 + bq3                            -> [B,1]
// where A[d, h*32+k] = W[h,d,k] (ripple einsum is a plain GEMM after
// re-layout), gate[j] = sigmoid(g[j>>5]).
// Round 1: fp32 SIMT SGEMM baseline (FFMA-pipe bound, ~38 TF ceiling).
// ---------------------------------------------------------------------------

#define NB 131072

__device__ float g_SA[(size_t)NB * 32];
__device__ float g_X1[(size_t)NB * 1024];
__device__ float g_X2[(size_t)NB * 1024];
__device__ float g_H1[(size_t)NB * 256];
__device__ float g_H2[(size_t)NB * 128];
__device__ float g_A1[32 * 1024];
__device__ float g_A2[1024 * 1024];
__device__ float g_GATE[64];   // [0:32) sigmoid(g1), [32:64) sigmoid(g2)

// ---------------------------------------------------------------------------
// Prep kernels
// ---------------------------------------------------------------------------

__global__ void prep_sa(const float* __restrict__ st, const float* __restrict__ ac,
                        float* __restrict__ sa, int M) {
    int idx = blockIdx.x * blockDim.x + threadIdx.x;
    if (idx >= M * 32) return;
    int b = idx >> 5, j = idx & 31;
    sa[idx] = (j < 24) ? st[b * 24 + j] : ac[b * 8 + (j - 24)];
}

// W[h, d, k] (h-major) -> A[d, h*32+k] row-major [D, 1024]
__global__ void prep_reindex(const float* __restrict__ W, float* __restrict__ A, int D) {
    int idx = blockIdx.x * blockDim.x + threadIdx.x;
    if (idx >= D * 1024) return;
    int j = idx & 1023;
    int d = idx >> 10;
    int h = j >> 5, k = j & 31;
    A[idx] = W[((size_t)h * D + d) * 32 + k];
}

__global__ void prep_gates(const float* __restrict__ g1, const float* __restrict__ g2,
                           float* __restrict__ out) {
    int t = threadIdx.x;
    if (t < 32)       out[t] = 1.0f / (1.0f + expf(-g1[t]));
    else if (t < 64)  out[t] = 1.0f / (1.0f + expf(-g2[t - 32]));
}

// ---------------------------------------------------------------------------
// SGEMM: C[M,N] = A[M,K] @ B[K,N], 128x128 tile, BK=16, 8x8 per thread,
// double-buffered smem. Requires M%128==0, N%128==0, K%16==0 (all hold here).
// EPI==0: C = tanh(acc + bias[col]) * gate[col>>5]    (ripple)
// EPI==1: C = acc + bias[col]                          (pre-LN linear)
// ---------------------------------------------------------------------------

template <int EPI>
__global__ void __launch_bounds__(256)
sgemm128(const float* __restrict__ A, const float* __restrict__ B,
         float* __restrict__ C, int M, int N, int K,
         const float* __restrict__ bias, const float* __restrict__ gate) {
    constexpr int BM = 128, BN = 128, BK = 16;
    __shared__ float As[2][BK][BM];
    __shared__ float Bs[2][BK][BN];

    const int tid = threadIdx.x;
    const int tx = tid & 15;   // N direction (thread tile col)
    const int ty = tid >> 4;   // M direction (thread tile row)

    const size_t bm = (size_t)blockIdx.y * BM;
    const int bn = blockIdx.x * BN;

    // global->smem load mapping
    const int a_row = tid >> 2;          // 0..63  (and +64)
    const int a_col = (tid & 3) << 2;    // 0,4,8,12
    const int b_row = tid >> 5;          // 0..7   (and +8)
    const int b_col = (tid & 31) << 2;   // 0..124

    const float* Ap = A + bm * (size_t)K;
    const float* Bp = B + bn;

    float4 pa0, pa1, pb0, pb1;

    // prologue: tile k0=0 -> buffer 0
    pa0 = *(const float4*)(Ap + (size_t)a_row * K + a_col);
    pa1 = *(const float4*)(Ap + (size_t)(a_row + 64) * K + a_col);
    pb0 = *(const float4*)(Bp + (size_t)b_row * N + b_col);
    pb1 = *(const float4*)(Bp + (size_t)(b_row + 8) * N + b_col);
    As[0][a_col + 0][a_row] = pa0.x;
    As[0][a_col + 1][a_row] = pa0.y;
    As[0][a_col + 2][a_row] = pa0.z;
    As[0][a_col + 3][a_row] = pa0.w;
    As[0][a_col + 0][a_row + 64] = pa1.x;
    As[0][a_col + 1][a_row + 64] = pa1.y;
    As[0][a_col + 2][a_row + 64] = pa1.z;
    As[0][a_col + 3][a_row + 64] = pa1.w;
    *(float4*)&Bs[0][b_row][b_col] = pb0;
    *(float4*)&Bs[0][b_row + 8][b_col] = pb1;
    __syncthreads();

    float acc[8][8];
#pragma unroll
    for (int i = 0; i < 8; i++)
#pragma unroll
        for (int j = 0; j < 8; j++) acc[i][j] = 0.0f;

    const int nk = K / BK;
    for (int kt = 0; kt < nk; kt++) {
        const int buf = kt & 1;
        if (kt + 1 < nk) {
            const int k0 = (kt + 1) * BK;
            pa0 = *(const float4*)(Ap + (size_t)a_row * K + k0 + a_col);
            pa1 = *(const float4*)(Ap + (size_t)(a_row + 64) * K + k0 + a_col);
            pb0 = *(const float4*)(Bp + (size_t)(k0 + b_row) * N + b_col);
            pb1 = *(const float4*)(Bp + (size_t)(k0 + b_row + 8) * N + b_col);
        }
#pragma unroll
        for (int k = 0; k < BK; k++) {
            float af[8], bf[8];
            *(float4*)&af[0] = *(const float4*)&As[buf][k][ty * 8];
            *(float4*)&af[4] = *(const float4*)&As[buf][k][ty * 8 + 4];
            *(float4*)&bf[0] = *(const float4*)&Bs[buf][k][tx * 8];
            *(float4*)&bf[4] = *(const float4*)&Bs[buf][k][tx * 8 + 4];
#pragma unroll
            for (int i = 0; i < 8; i++)
#pragma unroll
                for (int j = 0; j < 8; j++)
                    acc[i][j] = fmaf(af[i], bf[j], acc[i][j]);
        }
        if (kt + 1 < nk) {
            const int nb = buf ^ 1;
            As[nb][a_col + 0][a_row] = pa0.x;
            As[nb][a_col + 1][a_row] = pa0.y;
            As[nb][a_col + 2][a_row] = pa0.z;
            As[nb][a_col + 3][a_row] = pa0.w;
            As[nb][a_col + 0][a_row + 64] = pa1.x;
            As[nb][a_col + 1][a_row + 64] = pa1.y;
            As[nb][a_col + 2][a_row + 64] = pa1.z;
            As[nb][a_col + 3][a_row + 64] = pa1.w;
            *(float4*)&Bs[nb][b_row][b_col] = pb0;
            *(float4*)&Bs[nb][b_row + 8][b_col] = pb1;
            __syncthreads();
        }
    }

    // epilogue
    const int col0 = bn + tx * 8;
    float bfr[8];
    *(float4*)&bfr[0] = *(const float4*)(bias + col0);
    *(float4*)&bfr[4] = *(const float4*)(bias + col0 + 4);
    float gv = 0.0f;
    if (EPI == 0) gv = gate[col0 >> 5];   // tx*8 block of 8 cols never crosses a 32-col head

#pragma unroll
    for (int i = 0; i < 8; i++) {
        const size_t row = bm + (size_t)(ty * 8 + i);
        float ov[8];
#pragma unroll
        for (int j = 0; j < 8; j++) {
            float v = acc[i][j] + bfr[j];
            ov[j] = (EPI == 0) ? (tanhf(v) * gv) : v;
        }
        *(float4*)(C + row * N + col0) = *(float4*)&ov[0];
        *(float4*)(C + row * N + col0 + 4) = *(float4*)&ov[4];
    }
}

// ---------------------------------------------------------------------------
// LayerNorm + ReLU, in place, one warp per row
// ---------------------------------------------------------------------------

template <int D>
__global__ void ln_relu_kernel(float* __restrict__ X, const float* __restrict__ gm,
                               const float* __restrict__ bt, int M) {
    const int wpb = blockDim.x >> 5;
    const int row = blockIdx.x * wpb + (threadIdx.x >> 5);
    if (row >= M) return;
    const int lane = threadIdx.x & 31;
    constexpr int PT = D / 32;
    float v[PT];
    float* rp = X + (size_t)row * D;
    float s = 0.0f;
#pragma unroll
    for (int i = 0; i < PT; i++) { v[i] = rp[lane + 32 * i]; s += v[i]; }
#pragma unroll
    for (int o = 16; o; o >>= 1) s += __shfl_xor_sync(0xffffffffu, s, o);
    const float mu = s * (1.0f / D);
    float vs = 0.0f;
#pragma unroll
    for (int i = 0; i < PT; i++) { float d = v[i] - mu; vs += d * d; }
#pragma unroll
    for (int o = 16; o; o >>= 1) vs += __shfl_xor_sync(0xffffffffu, vs, o);
    const float inv = rsqrtf(vs * (1.0f / D) + 1e-5f);
#pragma unroll
    for (int i = 0; i < PT; i++) {
        float y = (v[i] - mu) * inv * gm[lane + 32 * i] + bt[lane + 32 * i];
        rp[lane + 32 * i] = fmaxf(y, 0.0f);
    }
}

// ---------------------------------------------------------------------------
// Final [B,128] @ [128,1] + b : one warp per row
// ---------------------------------------------------------------------------

__global__ void final_dot(const float* __restrict__ H, const float* __restrict__ w,
                          const float* __restrict__ b, float* __restrict__ out, int M) {
    const int wpb = blockDim.x >> 5;
    const int row = blockIdx.x * wpb + (threadIdx.x >> 5);
    if (row >= M) return;
    const int lane = threadIdx.x & 31;
    const float4 hv = *(const float4*)(H + (size_t)row * 128 + lane * 4);
    const float4 wv = *(const float4*)(w + lane * 4);
    float s = hv.x * wv.x + hv.y * wv.y + hv.z * wv.z + hv.w * wv.w;
#pragma unroll
    for (int o = 16; o; o >>= 1) s += __shfl_xor_sync(0xffffffffu, s, o);
    if (lane == 0) out[row] = s + b[0];
}

// ---------------------------------------------------------------------------
// launch
// ---------------------------------------------------------------------------

extern "C" void kernel_launch(void* const* d_in, const int* in_sizes, int n_in,
                              void* d_out, int out_size) {
    const float* state = (const float*)d_in[0];
    const float* action = (const float*)d_in[1];
    const float* W1   = (const float*)d_in[2];
    const float* b1   = (const float*)d_in[3];
    const float* g1   = (const float*)d_in[4];
    const float* W2   = (const float*)d_in[5];
    const float* b2   = (const float*)d_in[6];
    const float* g2   = (const float*)d_in[7];
    const float* Wq1  = (const float*)d_in[8];
    const float* bq1  = (const float*)d_in[9];
    const float* ln1g = (const float*)d_in[10];
    const float* ln1b = (const float*)d_in[11];
    const float* Wq2  = (const float*)d_in[12];
    const float* bq2  = (const float*)d_in[13];
    const float* ln2g = (const float*)d_in[14];
    const float* ln2b = (const float*)d_in[15];
    const float* Wq3  = (const float*)d_in[16];
    const float* bq3  = (const float*)d_in[17];
    float* out = (float*)d_out;

    const int M = in_sizes[0] / 24;
    if (M <= 0) return;

    float *sa, *x1, *x2, *h1, *h2, *a1, *a2, *gt;
    cudaGetSymbolAddress((void**)&sa, g_SA);
    cudaGetSymbolAddress((void**)&x1, g_X1);
    cudaGetSymbolAddress((void**)&x2, g_X2);
    cudaGetSymbolAddress((void**)&h1, g_H1);
    cudaGetSymbolAddress((void**)&h2, g_H2);
    cudaGetSymbolAddress((void**)&a1, g_A1);
    cudaGetSymbolAddress((void**)&a2, g_A2);
    cudaGetSymbolAddress((void**)&gt, g_GATE);

    // prep
    prep_sa<<<(M * 32 + 255) / 256, 256>>>(state, action, sa, M);
    prep_reindex<<<(32 * 1024 + 255) / 256, 256>>>(W1, a1, 32);
    prep_reindex<<<(1024 * 1024 + 255) / 256, 256>>>(W2, a2, 1024);
    prep_gates<<<1, 64>>>(g1, g2, gt);

    const int MB = M / 128;   // 1024 row tiles

    // G0: [M,32] @ [32,1024], tanh*gate1
    sgemm128<0><<<dim3(8, MB), 256>>>(sa, a1, x1, M, 1024, 32, b1, gt);
    // G1: [M,1024] @ [1024,1024], tanh*gate2   (dominant)
    sgemm128<0><<<dim3(8, MB), 256>>>(x1, a2, x2, M, 1024, 1024, b2, gt + 32);
    // G2: [M,1024] @ [1024,256] + bq1
    sgemm128<1><<<dim3(2, MB), 256>>>(x2, Wq1, h1, M, 256, 1024, bq1, nullptr);
    ln_relu_kernel<256><<<(M + 7) / 8, 256>>>(h1, ln1g, ln1b, M);
    // G3: [M,256] @ [256,128] + bq2
    sgemm128<1><<<dim3(1, MB), 256>>>(h1, Wq2, h2, M, 128, 256, bq2, nullptr);
    ln_relu_kernel<128><<<(M + 7) / 8, 256>>>(h2, ln2g, ln2b, M);
    // G4: [M,128] @ [128,1] + bq3
    final_dot<<<(M + 7) / 8, 256>>>(h2, Wq3, bq3, out, M);
}

// round 5
// speedup vs baseline: 2.9972x; 2.9972x over previous
#include <cuda_runtime.h>
#include <cuda_bf16.h>
#include <math.h>
#include <stdint.h>

// ===========================================================================
// COR_Critic — bf16 hi/lo 3-pass split on mma.sync (HMMA) + ldmatrix +
// cp.async. (tcgen05 PTX rejected: harness lowers via compute_103
// family-generic target, which forbids arch-specific 'a' features.)
//   sa  = concat(state, action) -> [B,32] (padded to 64)
//   X1  = tanh(sa @ A1 + b1) * gate1      -> [B,1024]
//   X2  = tanh(X1 @ A2 + b2) * gate2      -> [B,1024]
//   H1p = X2 @ Wq1 + bq1                  -> [B,256]
//   H1  = relu(LN(H1p))  (bf16 hi/lo)
//   H2p = H1 @ Wq2 + bq2                  -> [B,128]
//   out = relu(LN(H2p)) @ Wq3 + bq3
// Split: x = hi + lo (both bf16); A@B ~= Ah@Bh + Ah@Bl + Al@Bh.
// ===========================================================================

#define NB 131072
using bf16 = __nv_bfloat16;

// ---------------- device scratch (static, no allocation) -------------------
__device__ bf16 g_SAh[(size_t)NB * 64];
__device__ bf16 g_SAl[(size_t)NB * 64];
__device__ bf16 g_W1th[1024 * 64],   g_W1tl[1024 * 64];
__device__ bf16 g_W2th[1024 * 1024], g_W2tl[1024 * 1024];
__device__ bf16 g_Q1th[256 * 1024],  g_Q1tl[256 * 1024];
__device__ bf16 g_Q2th[128 * 256],   g_Q2tl[128 * 256];
__device__ bf16 g_X1h[(size_t)NB * 1024], g_X1l[(size_t)NB * 1024];
__device__ bf16 g_X2h[(size_t)NB * 1024], g_X2l[(size_t)NB * 1024];
__device__ float g_H1p[(size_t)NB * 256];
__device__ bf16 g_H1h[(size_t)NB * 256], g_H1l[(size_t)NB * 256];
__device__ float g_H2p[(size_t)NB * 128];
__device__ float g_GATE[64];

// ---------------- PTX helpers ----------------------------------------------
__device__ __forceinline__ uint32_t smem_u32(const void* p) {
    uint32_t a;
    asm("{ .reg .u64 t; cvta.to.shared.u64 t, %1; cvt.u32.u64 %0, t; }"
        : "=r"(a) : "l"(p));
    return a;
}
__device__ __forceinline__ void cp16(uint32_t s, const void* g) {
    asm volatile("cp.async.cg.shared.global [%0], [%1], 16;" :: "r"(s), "l"(g));
}
#define CP_COMMIT() asm volatile("cp.async.commit_group;" ::: "memory")
__device__ __forceinline__ void ldsm4(uint32_t* r, uint32_t a) {
    asm volatile("ldmatrix.sync.aligned.m8n8.x4.shared.b16 {%0,%1,%2,%3}, [%4];"
                 : "=r"(r[0]), "=r"(r[1]), "=r"(r[2]), "=r"(r[3]) : "r"(a));
}
__device__ __forceinline__ void ldsm2(uint32_t* r, uint32_t a) {
    asm volatile("ldmatrix.sync.aligned.m8n8.x2.shared.b16 {%0,%1}, [%2];"
                 : "=r"(r[0]), "=r"(r[1]) : "r"(a));
}
__device__ __forceinline__ void mma16816(float* d, const uint32_t* a, const uint32_t* b) {
    asm volatile(
        "mma.sync.aligned.m16n8k16.row.col.f32.bf16.bf16.f32 "
        "{%0,%1,%2,%3}, {%4,%5,%6,%7}, {%8,%9}, {%0,%1,%2,%3};"
        : "+f"(d[0]), "+f"(d[1]), "+f"(d[2]), "+f"(d[3])
        : "r"(a[0]), "r"(a[1]), "r"(a[2]), "r"(a[3]), "r"(b[0]), "r"(b[1]));
}
__device__ __forceinline__ void split_bf(float x, bf16& h, bf16& l) {
    h = __float2bfloat16_rn(x);
    l = __float2bfloat16_rn(x - __bfloat162float(h));
}

// ---------------- prep kernels ---------------------------------------------
__global__ void prep_sa2(const float* __restrict__ st, const float* __restrict__ ac,
                         bf16* __restrict__ h, bf16* __restrict__ l, int M) {
    int idx = blockIdx.x * blockDim.x + threadIdx.x;
    if (idx >= M * 64) return;
    int b = idx >> 6, j = idx & 63;
    float v = 0.f;
    if (j < 24) v = st[b * 24 + j];
    else if (j < 32) v = ac[b * 8 + (j - 24)];
    bf16 hh, ll; split_bf(v, hh, ll);
    h[idx] = hh; l[idx] = ll;
}
// A1t[n,k] = W1[n>>5, k, n&31], k<32 else 0  (n<1024, k<64)
__global__ void prep_w1t(const float* __restrict__ W, bf16* __restrict__ h, bf16* __restrict__ l) {
    int idx = blockIdx.x * blockDim.x + threadIdx.x;
    if (idx >= 1024 * 64) return;
    int n = idx >> 6, k = idx & 63;
    float v = (k < 32) ? W[((size_t)((n >> 5) * 32 + k)) * 32 + (n & 31)] : 0.f;
    bf16 hh, ll; split_bf(v, hh, ll);
    h[idx] = hh; l[idx] = ll;
}
// A2t[n,k] = W2[n>>5, k, n&31]
__global__ void prep_w2t(const float* __restrict__ W, bf16* __restrict__ h, bf16* __restrict__ l) {
    int idx = blockIdx.x * blockDim.x + threadIdx.x;
    if (idx >= 1024 * 1024) return;
    int n = idx >> 10, k = idx & 1023;
    float v = W[((size_t)(n >> 5) * 1024 + k) * 32 + (n & 31)];
    bf16 hh, ll; split_bf(v, hh, ll);
    h[idx] = hh; l[idx] = ll;
}
// Qt[n,k] = Wq[k*N + n]
__global__ void prep_wt(const float* __restrict__ W, bf16* __restrict__ h, bf16* __restrict__ l,
                        int Nn, int K) {
    int idx = blockIdx.x * blockDim.x + threadIdx.x;
    if (idx >= Nn * K) return;
    int n = idx / K, k = idx - n * K;
    float v = W[(size_t)k * Nn + n];
    bf16 hh, ll; split_bf(v, hh, ll);
    h[idx] = hh; l[idx] = ll;
}
__global__ void prep_gates(const float* __restrict__ g1, const float* __restrict__ g2,
                           float* __restrict__ out) {
    int t = threadIdx.x;
    if (t < 32)      out[t] = 1.0f / (1.0f + expf(-g1[t]));
    else if (t < 64) out[t] = 1.0f / (1.0f + expf(-g2[t - 32]));
}

// ---------------- HMMA GEMM -------------------------------------------------
// C[M,N] = (Ah+Al)[M,K] @ (Bh+Bl)[N,K]^T, 3-pass split, fp32 acc in regs.
// BM=128, BN=128, BK=64, 8 warps (4m x 2n), warp tile 32x64.
// EPI 0: tanh(acc+bias)*gate -> Ch/Cl bf16.   EPI 1: acc+bias -> Cf fp32.
template <int EPI>
__global__ void __launch_bounds__(256)
mma_gemm(const bf16* __restrict__ Ah, const bf16* __restrict__ Al,
         const bf16* __restrict__ Bh, const bf16* __restrict__ Bl,
         int K, int ldC,
         const float* __restrict__ bias, const float* __restrict__ gate,
         float* __restrict__ Cf, bf16* __restrict__ Ch, bf16* __restrict__ Cl) {
    constexpr int TILE = 128 * 64 * 2;   // 16 KB per operand tile
    constexpr int BUF = 4 * TILE;        // Ah|Al|Bh|Bl

    extern __shared__ char dsm[];
    const uint32_t sb = (smem_u32(dsm) + 1023) & ~1023u;

    const int tid = threadIdx.x;
    const int wid = tid >> 5, lane = tid & 31;
    const int wm = wid >> 1, wn = wid & 1;
    const size_t bm = (size_t)blockIdx.y * 128;
    const int bn = blockIdx.x * 128;
    const int nk = K >> 6;

    auto load_tile = [&](int kt, int buf) {
        const uint32_t base = sb + buf * BUF;
#pragma unroll
        for (int i = 0; i < 4; i++) {
            const int c = tid + 256 * i;           // 0..1023
            const int row = c >> 3;
            const int cb = (c & 7) << 4;
            const uint32_t sw = (uint32_t)(row * 128) + (uint32_t)(cb ^ ((row & 7) << 4));
            const size_t kofs = (size_t)kt * 64 + ((c & 7) << 3);
            const size_t ga = (bm + row) * (size_t)K + kofs;
            const size_t gb = (size_t)(bn + row) * K + kofs;
            cp16(base + sw, Ah + ga);
            cp16(base + TILE + sw, Al + ga);
            cp16(base + 2 * TILE + sw, Bh + gb);
            cp16(base + 3 * TILE + sw, Bl + gb);
        }
    };

    // per-thread ldmatrix address components
    const int r15 = lane & 15, halfA = lane >> 4;
    int pA[2], xA[2];
#pragma unroll
    for (int mt = 0; mt < 2; mt++) {
        const int rowA = wm * 32 + mt * 16 + r15;
        pA[mt] = rowA * 128;
        xA[mt] = (rowA & 7) << 4;
    }
    const int l4 = lane & 15;
    const int l8 = l4 & 7, halfB = l4 >> 3;
    const int xB = l8 << 4;
    int pB[8];
#pragma unroll
    for (int nt = 0; nt < 8; nt++) pB[nt] = (wn * 64 + nt * 8 + l8) * 128;

    float acc[2][8][4];
#pragma unroll
    for (int mt = 0; mt < 2; mt++)
#pragma unroll
        for (int nt = 0; nt < 8; nt++)
#pragma unroll
            for (int q = 0; q < 4; q++) acc[mt][nt][q] = 0.f;

    load_tile(0, 0);
    CP_COMMIT();

    for (int kt = 0; kt < nk; kt++) {
        const int buf = kt & 1;
        if (kt + 1 < nk) {
            load_tile(kt + 1, buf ^ 1);
            CP_COMMIT();
            asm volatile("cp.async.wait_group 1;" ::: "memory");
        } else {
            asm volatile("cp.async.wait_group 0;" ::: "memory");
        }
        __syncthreads();

        const uint32_t tAh = sb + buf * BUF;
        const uint32_t tAl = tAh + TILE;
        const uint32_t tBh = tAh + 2 * TILE;
        const uint32_t tBl = tAh + 3 * TILE;

#pragma unroll
        for (int ks = 0; ks < 4; ks++) {
            const int kbA = ks * 32 + 16 * halfA;
            const int kbB = ks * 32 + 16 * halfB;
            uint32_t bfr[8][2], a[2][4];
            // B-hi frags
#pragma unroll
            for (int nt = 0; nt < 8; nt++)
                ldsm2(bfr[nt], tBh + pB[nt] + (kbB ^ xB));
            // pass 1: Ah * Bh
#pragma unroll
            for (int mt = 0; mt < 2; mt++)
                ldsm4(a[mt], tAh + pA[mt] + (kbA ^ xA[mt]));
#pragma unroll
            for (int mt = 0; mt < 2; mt++)
#pragma unroll
                for (int nt = 0; nt < 8; nt++)
                    mma16816(acc[mt][nt], a[mt], bfr[nt]);
            // pass 2: Al * Bh
#pragma unroll
            for (int mt = 0; mt < 2; mt++)
                ldsm4(a[mt], tAl + pA[mt] + (kbA ^ xA[mt]));
#pragma unroll
            for (int mt = 0; mt < 2; mt++)
#pragma unroll
                for (int nt = 0; nt < 8; nt++)
                    mma16816(acc[mt][nt], a[mt], bfr[nt]);
            // pass 3: Ah * Bl
#pragma unroll
            for (int nt = 0; nt < 8; nt++)
                ldsm2(bfr[nt], tBl + pB[nt] + (kbB ^ xB));
#pragma unroll
            for (int mt = 0; mt < 2; mt++)
                ldsm4(a[mt], tAh + pA[mt] + (kbA ^ xA[mt]));
#pragma unroll
            for (int mt = 0; mt < 2; mt++)
#pragma unroll
                for (int nt = 0; nt < 8; nt++)
                    mma16816(acc[mt][nt], a[mt], bfr[nt]);
        }
        __syncthreads();
    }

    // ---- epilogue (acc in regs) ----
    const int gid = lane >> 2, qd = lane & 3;
#pragma unroll
    for (int nt = 0; nt < 8; nt++) {
        const int c = bn + wn * 64 + nt * 8 + qd * 2;
        const float b0 = bias[c], b1 = bias[c + 1];
        float gv = 0.f;
        if (EPI == 0) gv = gate[c >> 5];
#pragma unroll
        for (int mt = 0; mt < 2; mt++) {
            const size_t r0 = bm + wm * 32 + mt * 16 + gid;
            if (EPI == 0) {
#pragma unroll
                for (int half = 0; half < 2; half++) {
                    const size_t row = r0 + 8 * half;
                    const float v0 = tanhf(acc[mt][nt][2 * half + 0] + b0) * gv;
                    const float v1 = tanhf(acc[mt][nt][2 * half + 1] + b1) * gv;
                    bf16 h0, l0, h1, l1;
                    split_bf(v0, h0, l0);
                    split_bf(v1, h1, l1);
                    *(uint32_t*)(Ch + row * (size_t)ldC + c) =
                        ((uint32_t)__bfloat16_as_ushort(h1) << 16) | __bfloat16_as_ushort(h0);
                    *(uint32_t*)(Cl + row * (size_t)ldC + c) =
                        ((uint32_t)__bfloat16_as_ushort(l1) << 16) | __bfloat16_as_ushort(l0);
                }
            } else {
#pragma unroll
                for (int half = 0; half < 2; half++) {
                    const size_t row = r0 + 8 * half;
                    float2 o;
                    o.x = acc[mt][nt][2 * half + 0] + b0;
                    o.y = acc[mt][nt][2 * half + 1] + b1;
                    *(float2*)(Cf + row * (size_t)ldC + c) = o;
                }
            }
        }
    }
}

// ---------------- LN + ReLU -> bf16 hi/lo (one warp per row) ---------------
template <int D>
__global__ void ln_relu_bf16(const float* __restrict__ X, const float* __restrict__ gm,
                             const float* __restrict__ bt, bf16* __restrict__ Yh,
                             bf16* __restrict__ Yl, int M) {
    const int row = blockIdx.x * (blockDim.x >> 5) + (threadIdx.x >> 5);
    if (row >= M) return;
    const int lane = threadIdx.x & 31;
    constexpr int PT = D / 32;
    float v[PT];
    const float* rp = X + (size_t)row * D;
    float s = 0.f;
#pragma unroll
    for (int i = 0; i < PT; i++) { v[i] = rp[lane + 32 * i]; s += v[i]; }
#pragma unroll
    for (int o = 16; o; o >>= 1) s += __shfl_xor_sync(0xffffffffu, s, o);
    const float mu = s * (1.0f / D);
    float vs = 0.f;
#pragma unroll
    for (int i = 0; i < PT; i++) { float d = v[i] - mu; vs += d * d; }
#pragma unroll
    for (int o = 16; o; o >>= 1) vs += __shfl_xor_sync(0xffffffffu, vs, o);
    const float inv = rsqrtf(vs * (1.0f / D) + 1e-5f);
#pragma unroll
    for (int i = 0; i < PT; i++) {
        float y = (v[i] - mu) * inv * gm[lane + 32 * i] + bt[lane + 32 * i];
        y = fmaxf(y, 0.f);
        bf16 h, l; split_bf(y, h, l);
        Yh[(size_t)row * D + lane + 32 * i] = h;
        Yl[(size_t)row * D + lane + 32 * i] = l;
    }
}

// ---------------- fused LN2 + ReLU + dot (one warp per row) ----------------
__global__ void ln2_dot(const float* __restrict__ X, const float* __restrict__ gm,
                        const float* __restrict__ bt, const float* __restrict__ w,
                        const float* __restrict__ b, float* __restrict__ out, int M) {
    const int row = blockIdx.x * (blockDim.x >> 5) + (threadIdx.x >> 5);
    if (row >= M) return;
    const int lane = threadIdx.x & 31;
    float v[4];
    const float* rp = X + (size_t)row * 128;
    float s = 0.f;
#pragma unroll
    for (int i = 0; i < 4; i++) { v[i] = rp[lane + 32 * i]; s += v[i]; }
#pragma unroll
    for (int o = 16; o; o >>= 1) s += __shfl_xor_sync(0xffffffffu, s, o);
    const float mu = s * (1.0f / 128.0f);
    float vs = 0.f;
#pragma unroll
    for (int i = 0; i < 4; i++) { float d = v[i] - mu; vs += d * d; }
#pragma unroll
    for (int o = 16; o; o >>= 1) vs += __shfl_xor_sync(0xffffffffu, vs, o);
    const float inv = rsqrtf(vs * (1.0f / 128.0f) + 1e-5f);
    float acc = 0.f;
#pragma unroll
    for (int i = 0; i < 4; i++) {
        float y = (v[i] - mu) * inv * gm[lane + 32 * i] + bt[lane + 32 * i];
        y = fmaxf(y, 0.f);
        acc = fmaf(y, w[lane + 32 * i], acc);
    }
#pragma unroll
    for (int o = 16; o; o >>= 1) acc += __shfl_xor_sync(0xffffffffu, acc, o);
    if (lane == 0) out[row] = acc + b[0];
}

// ---------------- launch ----------------------------------------------------
extern "C" void kernel_launch(void* const* d_in, const int* in_sizes, int n_in,
                              void* d_out, int out_size) {
    const float* state = (const float*)d_in[0];
    const float* action = (const float*)d_in[1];
    const float* W1 = (const float*)d_in[2];
    const float* b1 = (const float*)d_in[3];
    const float* g1 = (const float*)d_in[4];
    const float* W2 = (const float*)d_in[5];
    const float* b2 = (const float*)d_in[6];
    const float* g2 = (const float*)d_in[7];
    const float* Wq1 = (const float*)d_in[8];
    const float* bq1 = (const float*)d_in[9];
    const float* ln1g = (const float*)d_in[10];
    const float* ln1b = (const float*)d_in[11];
    const float* Wq2 = (const float*)d_in[12];
    const float* bq2 = (const float*)d_in[13];
    const float* ln2g = (const float*)d_in[14];
    const float* ln2b = (const float*)d_in[15];
    const float* Wq3 = (const float*)d_in[16];
    const float* bq3 = (const float*)d_in[17];
    float* out = (float*)d_out;

    const int M = in_sizes[0] / 24;
    if (M <= 0) return;

    bf16 *sah, *sal, *w1h, *w1l, *w2h, *w2l, *q1h, *q1l, *q2h, *q2l;
    bf16 *x1h, *x1l, *x2h, *x2l, *h1h, *h1l;
    float *h1p, *h2p, *gt;
    cudaGetSymbolAddress((void**)&sah, g_SAh);  cudaGetSymbolAddress((void**)&sal, g_SAl);
    cudaGetSymbolAddress((void**)&w1h, g_W1th); cudaGetSymbolAddress((void**)&w1l, g_W1tl);
    cudaGetSymbolAddress((void**)&w2h, g_W2th); cudaGetSymbolAddress((void**)&w2l, g_W2tl);
    cudaGetSymbolAddress((void**)&q1h, g_Q1th); cudaGetSymbolAddress((void**)&q1l, g_Q1tl);
    cudaGetSymbolAddress((void**)&q2h, g_Q2th); cudaGetSymbolAddress((void**)&q2l, g_Q2tl);
    cudaGetSymbolAddress((void**)&x1h, g_X1h);  cudaGetSymbolAddress((void**)&x1l, g_X1l);
    cudaGetSymbolAddress((void**)&x2h, g_X2h);  cudaGetSymbolAddress((void**)&x2l, g_X2l);
    cudaGetSymbolAddress((void**)&h1h, g_H1h);  cudaGetSymbolAddress((void**)&h1l, g_H1l);
    cudaGetSymbolAddress((void**)&h1p, g_H1p);  cudaGetSymbolAddress((void**)&h2p, g_H2p);
    cudaGetSymbolAddress((void**)&gt, g_GATE);

    const int SMEM = 2 * (4 * 128 * 64 * 2) + 1024;   // 132096 B
    cudaFuncSetAttribute(mma_gemm<0>, cudaFuncAttributeMaxDynamicSharedMemorySize, SMEM);
    cudaFuncSetAttribute(mma_gemm<1>, cudaFuncAttributeMaxDynamicSharedMemorySize, SMEM);

    // prep
    prep_sa2<<<(M * 64 + 255) / 256, 256>>>(state, action, sah, sal, M);
    prep_w1t<<<(1024 * 64 + 255) / 256, 256>>>(W1, w1h, w1l);
    prep_w2t<<<(1024 * 1024 + 255) / 256, 256>>>(W2, w2h, w2l);
    prep_wt<<<(256 * 1024 + 255) / 256, 256>>>(Wq1, q1h, q1l, 256, 1024);
    prep_wt<<<(128 * 256 + 255) / 256, 256>>>(Wq2, q2h, q2l, 128, 256);
    prep_gates<<<1, 64>>>(g1, g2, gt);

    const int MB = M / 128;

    // G0: [M,64pad] @ [1024,64]^T -> X1 (tanh * gate1)
    mma_gemm<0><<<dim3(8, MB), 256, SMEM>>>(sah, sal, w1h, w1l, 64, 1024,
                                            b1, gt, nullptr, x1h, x1l);
    // G1: [M,1024] @ [1024,1024]^T -> X2 (tanh * gate2)   (dominant)
    mma_gemm<0><<<dim3(8, MB), 256, SMEM>>>(x1h, x1l, w2h, w2l, 1024, 1024,
                                            b2, gt + 32, nullptr, x2h, x2l);
    // G2: [M,1024] @ [256,1024]^T -> H1p (+bq1)
    mma_gemm<1><<<dim3(2, MB), 256, SMEM>>>(x2h, x2l, q1h, q1l, 1024, 256,
                                            bq1, nullptr, h1p, nullptr, nullptr);
    ln_relu_bf16<256><<<(M + 7) / 8, 256>>>(h1p, ln1g, ln1b, h1h, h1l, M);
    // G3: [M,256] @ [128,256]^T -> H2p (+bq2)
    mma_gemm<1><<<dim3(1, MB), 256, SMEM>>>(h1h, h1l, q2h, q2l, 256, 128,
                                            bq2, nullptr, h2p, nullptr, nullptr);
    ln2_dot<<<(M + 7) / 8, 256>>>(h2p, ln2g, ln2b, Wq3, bq3, out, M);
}

// round 7
// speedup vs baseline: 5.0497x; 1.6848x over previous
#include <cuda_runtime.h>
#include <cuda_fp16.h>
#include <math.h>
#include <stdint.h>

// ===========================================================================
// COR_Critic — fp16 2-pass split on mma.sync (HMMA) + ldmatrix + cp.async.
// Activations: single fp16 (rn).  Weights: fp16 hi + lo (lo captures the
// rounding residual; subnormal-range values are fine on tensor cores).
// C = Af @ (Wh + Wl): only error is activation rounding (~7e-5/GEMM RMS).
//   sa  = concat(state, action) -> [B,32] (padded to 64)
//   X1  = tanh(sa @ A1 + b1) * gate1      -> [B,1024]
//   X2  = tanh(X1 @ A2 + b2) * gate2      -> [B,1024]
//   H1p = X2 @ Wq1 + bq1 ; H1 = relu(LN(H1p))  (fp16)
//   H2p = H1 @ Wq2 + bq2 ; out = relu(LN(H2p)) @ Wq3 + bq3
// ===========================================================================

#define NB 131072
using fp16 = __half;

// ---------------- device scratch (static, no allocation) -------------------
__device__ fp16 g_SAf[(size_t)NB * 64];
__device__ fp16 g_W1th[1024 * 64],   g_W1tl[1024 * 64];
__device__ fp16 g_W2th[1024 * 1024], g_W2tl[1024 * 1024];
__device__ fp16 g_Q1th[256 * 1024],  g_Q1tl[256 * 1024];
__device__ fp16 g_Q2th[128 * 256],   g_Q2tl[128 * 256];
__device__ fp16 g_X1f[(size_t)NB * 1024];
__device__ fp16 g_X2f[(size_t)NB * 1024];
__device__ float g_H1p[(size_t)NB * 256];
__device__ fp16 g_H1f[(size_t)NB * 256];
__device__ float g_H2p[(size_t)NB * 128];
__device__ float g_GATE[64];

// ---------------- PTX helpers ----------------------------------------------
__device__ __forceinline__ uint32_t smem_u32(const void* p) {
    uint32_t a;
    asm("{ .reg .u64 t; cvta.to.shared.u64 t, %1; cvt.u32.u64 %0, t; }"
        : "=r"(a) : "l"(p));
    return a;
}
__device__ __forceinline__ void cp16(uint32_t s, const void* g) {
    asm volatile("cp.async.cg.shared.global [%0], [%1], 16;" :: "r"(s), "l"(g));
}
#define CP_COMMIT() asm volatile("cp.async.commit_group;" ::: "memory")
__device__ __forceinline__ void ldsm4(uint32_t* r, uint32_t a) {
    asm volatile("ldmatrix.sync.aligned.m8n8.x4.shared.b16 {%0,%1,%2,%3}, [%4];"
                 : "=r"(r[0]), "=r"(r[1]), "=r"(r[2]), "=r"(r[3]) : "r"(a));
}
__device__ __forceinline__ void ldsm2(uint32_t* r, uint32_t a) {
    asm volatile("ldmatrix.sync.aligned.m8n8.x2.shared.b16 {%0,%1}, [%2];"
                 : "=r"(r[0]), "=r"(r[1]) : "r"(a));
}
__device__ __forceinline__ void mma16816(float* d, const uint32_t* a, const uint32_t* b) {
    asm volatile(
        "mma.sync.aligned.m16n8k16.row.col.f32.f16.f16.f32 "
        "{%0,%1,%2,%3}, {%4,%5,%6,%7}, {%8,%9}, {%0,%1,%2,%3};"
        : "+f"(d[0]), "+f"(d[1]), "+f"(d[2]), "+f"(d[3])
        : "r"(a[0]), "r"(a[1]), "r"(a[2]), "r"(a[3]), "r"(b[0]), "r"(b[1]));
}
__device__ __forceinline__ void split_h(float x, fp16& h, fp16& l) {
    h = __float2half_rn(x);
    l = __float2half_rn(x - __half2float(h));
}

// ---------------- prep kernels ---------------------------------------------
__global__ void prep_saf(const float* __restrict__ st, const float* __restrict__ ac,
                         fp16* __restrict__ o, int M) {
    int idx = blockIdx.x * blockDim.x + threadIdx.x;
    if (idx >= M * 64) return;
    int b = idx >> 6, j = idx & 63;
    float v = 0.f;
    if (j < 24) v = st[b * 24 + j];
    else if (j < 32) v = ac[b * 8 + (j - 24)];
    o[idx] = __float2half_rn(v);
}
// A1t[n,k] = W1[n>>5, k, n&31], k<32 else 0
__global__ void prep_w1t(const float* __restrict__ W, fp16* __restrict__ h, fp16* __restrict__ l) {
    int idx = blockIdx.x * blockDim.x + threadIdx.x;
    if (idx >= 1024 * 64) return;
    int n = idx >> 6, k = idx & 63;
    float v = (k < 32) ? W[((size_t)((n >> 5) * 32 + k)) * 32 + (n & 31)] : 0.f;
    fp16 hh, ll; split_h(v, hh, ll);
    h[idx] = hh; l[idx] = ll;
}
// A2t[n,k] = W2[n>>5, k, n&31]
__global__ void prep_w2t(const float* __restrict__ W, fp16* __restrict__ h, fp16* __restrict__ l) {
    int idx = blockIdx.x * blockDim.x + threadIdx.x;
    if (idx >= 1024 * 1024) return;
    int n = idx >> 10, k = idx & 1023;
    float v = W[((size_t)(n >> 5) * 1024 + k) * 32 + (n & 31)];
    fp16 hh, ll; split_h(v, hh, ll);
    h[idx] = hh; l[idx] = ll;
}
// Qt[n,k] = Wq[k*N + n]
__global__ void prep_wt(const float* __restrict__ W, fp16* __restrict__ h, fp16* __restrict__ l,
                        int Nn, int K) {
    int idx = blockIdx.x * blockDim.x + threadIdx.x;
    if (idx >= Nn * K) return;
    int n = idx / K, k = idx - n * K;
    float v = W[(size_t)k * Nn + n];
    fp16 hh, ll; split_h(v, hh, ll);
    h[idx] = hh; l[idx] = ll;
}
__global__ void prep_gates(const float* __restrict__ g1, const float* __restrict__ g2,
                           float* __restrict__ out) {
    int t = threadIdx.x;
    if (t < 32)      out[t] = 1.0f / (1.0f + expf(-g1[t]));
    else if (t < 64) out[t] = 1.0f / (1.0f + expf(-g2[t - 32]));
}

// ---------------- HMMA GEMM -------------------------------------------------
// C[M,N] = Af[M,K] @ (Wh+Wl)[N,K]^T, fp32 acc in regs.
// BM=128, BN=128, BK=64, 8 warps (4m x 2n), warp tile 32x64.
// EPI 0: tanh(acc+bias)*gate -> Cfp16.   EPI 1: acc+bias -> Cf fp32.
template <int EPI>
__global__ void __launch_bounds__(256)
mma_gemm(const fp16* __restrict__ Af,
         const fp16* __restrict__ Bh, const fp16* __restrict__ Bl,
         int K, int ldC,
         const float* __restrict__ bias, const float* __restrict__ gate,
         float* __restrict__ Cf, fp16* __restrict__ Ch) {
    constexpr int TILE = 128 * 64 * 2;   // 16 KB per operand tile
    constexpr int BUF = 3 * TILE;        // Af | Bh | Bl

    extern __shared__ char dsm[];
    const uint32_t sb = (smem_u32(dsm) + 1023) & ~1023u;

    const int tid = threadIdx.x;
    const int wid = tid >> 5, lane = tid & 31;
    const int wm = wid >> 1, wn = wid & 1;
    const size_t bm = (size_t)blockIdx.y * 128;
    const int bn = blockIdx.x * 128;
    const int nk = K >> 6;

    auto load_tile = [&](int kt, int buf) {
        const uint32_t base = sb + buf * BUF;
#pragma unroll
        for (int i = 0; i < 4; i++) {
            const int c = tid + 256 * i;           // 0..1023
            const int row = c >> 3;
            const int cb = (c & 7) << 4;
            const uint32_t sw = (uint32_t)(row * 128) + (uint32_t)(cb ^ ((row & 7) << 4));
            const size_t kofs = (size_t)kt * 64 + ((c & 7) << 3);
            const size_t ga = (bm + row) * (size_t)K + kofs;
            const size_t gb = (size_t)(bn + row) * K + kofs;
            cp16(base + sw, Af + ga);
            cp16(base + TILE + sw, Bh + gb);
            cp16(base + 2 * TILE + sw, Bl + gb);
        }
    };

    // per-thread ldmatrix address components
    const int r15 = lane & 15, halfA = lane >> 4;
    int pA[2], xA[2];
#pragma unroll
    for (int mt = 0; mt < 2; mt++) {
        const int rowA = wm * 32 + mt * 16 + r15;
        pA[mt] = rowA * 128;
        xA[mt] = (rowA & 7) << 4;
    }
    const int l4 = lane & 15;
    const int l8 = l4 & 7, halfB = l4 >> 3;
    const int xB = l8 << 4;
    int pB[8];
#pragma unroll
    for (int nt = 0; nt < 8; nt++) pB[nt] = (wn * 64 + nt * 8 + l8) * 128;

    float acc[2][8][4];
#pragma unroll
    for (int mt = 0; mt < 2; mt++)
#pragma unroll
        for (int nt = 0; nt < 8; nt++)
#pragma unroll
            for (int q = 0; q < 4; q++) acc[mt][nt][q] = 0.f;

    load_tile(0, 0);
    CP_COMMIT();

    for (int kt = 0; kt < nk; kt++) {
        const int buf = kt & 1;
        if (kt + 1 < nk) {
            load_tile(kt + 1, buf ^ 1);
            CP_COMMIT();
            asm volatile("cp.async.wait_group 1;" ::: "memory");
        } else {
            asm volatile("cp.async.wait_group 0;" ::: "memory");
        }
        __syncthreads();

        const uint32_t tA = sb + buf * BUF;
        const uint32_t tBh = tA + TILE;
        const uint32_t tBl = tA + 2 * TILE;

#pragma unroll
        for (int ks = 0; ks < 4; ks++) {
            const int kbA = ks * 32 + 16 * halfA;
            const int kbB = ks * 32 + 16 * halfB;
            uint32_t a[2][4], bfr[8][2];
#pragma unroll
            for (int mt = 0; mt < 2; mt++)
                ldsm4(a[mt], tA + pA[mt] + (kbA ^ xA[mt]));
            // pass 1: Af * Wh
#pragma unroll
            for (int nt = 0; nt < 8; nt++)
                ldsm2(bfr[nt], tBh + pB[nt] + (kbB ^ xB));
#pragma unroll
            for (int mt = 0; mt < 2; mt++)
#pragma unroll
                for (int nt = 0; nt < 8; nt++)
                    mma16816(acc[mt][nt], a[mt], bfr[nt]);
            // pass 2: Af * Wl
#pragma unroll
            for (int nt = 0; nt < 8; nt++)
                ldsm2(bfr[nt], tBl + pB[nt] + (kbB ^ xB));
#pragma unroll
            for (int mt = 0; mt < 2; mt++)
#pragma unroll
                for (int nt = 0; nt < 8; nt++)
                    mma16816(acc[mt][nt], a[mt], bfr[nt]);
        }
        __syncthreads();
    }

    // ---- epilogue (acc in regs) ----
    const int gid = lane >> 2, qd = lane & 3;
#pragma unroll
    for (int nt = 0; nt < 8; nt++) {
        const int c = bn + wn * 64 + nt * 8 + qd * 2;
        const float b0 = bias[c], b1 = bias[c + 1];
        float gv = 0.f;
        if (EPI == 0) gv = gate[c >> 5];
#pragma unroll
        for (int mt = 0; mt < 2; mt++) {
            const size_t r0 = bm + wm * 32 + mt * 16 + gid;
            if (EPI == 0) {
#pragma unroll
                for (int half = 0; half < 2; half++) {
                    const size_t row = r0 + 8 * half;
                    const float v0 = tanhf(acc[mt][nt][2 * half + 0] + b0) * gv;
                    const float v1 = tanhf(acc[mt][nt][2 * half + 1] + b1) * gv;
                    const fp16 h0 = __float2half_rn(v0);
                    const fp16 h1 = __float2half_rn(v1);
                    *(uint32_t*)(Ch + row * (size_t)ldC + c) =
                        ((uint32_t)__half_as_ushort(h1) << 16) | __half_as_ushort(h0);
                }
            } else {
#pragma unroll
                for (int half = 0; half < 2; half++) {
                    const size_t row = r0 + 8 * half;
                    float2 o;
                    o.x = acc[mt][nt][2 * half + 0] + b0;
                    o.y = acc[mt][nt][2 * half + 1] + b1;
                    *(float2*)(Cf + row * (size_t)ldC + c) = o;
                }
            }
        }
    }
}

// ---------------- LN + ReLU -> fp16 (one warp per row) ---------------------
template <int D>
__global__ void ln_relu_f16(const float* __restrict__ X, const float* __restrict__ gm,
                            const float* __restrict__ bt, fp16* __restrict__ Y, int M) {
    const int row = blockIdx.x * (blockDim.x >> 5) + (threadIdx.x >> 5);
    if (row >= M) return;
    const int lane = threadIdx.x & 31;
    constexpr int PT = D / 32;
    float v[PT];
    const float* rp = X + (size_t)row * D;
    float s = 0.f;
#pragma unroll
    for (int i = 0; i < PT; i++) { v[i] = rp[lane + 32 * i]; s += v[i]; }
#pragma unroll
    for (int o = 16; o; o >>= 1) s += __shfl_xor_sync(0xffffffffu, s, o);
    const float mu = s * (1.0f / D);
    float vs = 0.f;
#pragma unroll
    for (int i = 0; i < PT; i++) { float d = v[i] - mu; vs += d * d; }
#pragma unroll
    for (int o = 16; o; o >>= 1) vs += __shfl_xor_sync(0xffffffffu, vs, o);
    const float inv = rsqrtf(vs * (1.0f / D) + 1e-5f);
#pragma unroll
    for (int i = 0; i < PT; i++) {
        float y = (v[i] - mu) * inv * gm[lane + 32 * i] + bt[lane + 32 * i];
        Y[(size_t)row * D + lane + 32 * i] = __float2half_rn(fmaxf(y, 0.f));
    }
}

// ---------------- fused LN2 + ReLU + dot (one warp per row) ----------------
__global__ void ln2_dot(const float* __restrict__ X, const float* __restrict__ gm,
                        const float* __restrict__ bt, const float* __restrict__ w,
                        const float* __restrict__ b, float* __restrict__ out, int M) {
    const int row = blockIdx.x * (blockDim.x >> 5) + (threadIdx.x >> 5);
    if (row >= M) return;
    const int lane = threadIdx.x & 31;
    float v[4];
    const float* rp = X + (size_t)row * 128;
    float s = 0.f;
#pragma unroll
    for (int i = 0; i < 4; i++) { v[i] = rp[lane + 32 * i]; s += v[i]; }
#pragma unroll
    for (int o = 16; o; o >>= 1) s += __shfl_xor_sync(0xffffffffu, s, o);
    const float mu = s * (1.0f / 128.0f);
    float vs = 0.f;
#pragma unroll
    for (int i = 0; i < 4; i++) { float d = v[i] - mu; vs += d * d; }
#pragma unroll
    for (int o = 16; o; o >>= 1) vs += __shfl_xor_sync(0xffffffffu, vs, o);
    const float inv = rsqrtf(vs * (1.0f / 128.0f) + 1e-5f);
    float acc = 0.f;
#pragma unroll
    for (int i = 0; i < 4; i++) {
        float y = (v[i] - mu) * inv * gm[lane + 32 * i] + bt[lane + 32 * i];
        y = fmaxf(y, 0.f);
        acc = fmaf(y, w[lane + 32 * i], acc);
    }
#pragma unroll
    for (int o = 16; o; o >>= 1) acc += __shfl_xor_sync(0xffffffffu, acc, o);
    if (lane == 0) out[row] = acc + b[0];
}

// ---------------- launch ----------------------------------------------------
extern "C" void kernel_launch(void* const* d_in, const int* in_sizes, int n_in,
                              void* d_out, int out_size) {
    const float* state = (const float*)d_in[0];
    const float* action = (const float*)d_in[1];
    const float* W1 = (const float*)d_in[2];
    const float* b1 = (const float*)d_in[3];
    const float* g1 = (const float*)d_in[4];
    const float* W2 = (const float*)d_in[5];
    const float* b2 = (const float*)d_in[6];
    const float* g2 = (const float*)d_in[7];
    const float* Wq1 = (const float*)d_in[8];
    const float* bq1 = (const float*)d_in[9];
    const float* ln1g = (const float*)d_in[10];
    const float* ln1b = (const float*)d_in[11];
    const float* Wq2 = (const float*)d_in[12];
    const float* bq2 = (const float*)d_in[13];
    const float* ln2g = (const float*)d_in[14];
    const float* ln2b = (const float*)d_in[15];
    const float* Wq3 = (const float*)d_in[16];
    const float* bq3 = (const float*)d_in[17];
    float* out = (float*)d_out;

    const int M = in_sizes[0] / 24;
    if (M <= 0) return;

    fp16 *saf, *w1h, *w1l, *w2h, *w2l, *q1h, *q1l, *q2h, *q2l, *x1f, *x2f, *h1f;
    float *h1p, *h2p, *gt;
    cudaGetSymbolAddress((void**)&saf, g_SAf);
    cudaGetSymbolAddress((void**)&w1h, g_W1th); cudaGetSymbolAddress((void**)&w1l, g_W1tl);
    cudaGetSymbolAddress((void**)&w2h, g_W2th); cudaGetSymbolAddress((void**)&w2l, g_W2tl);
    cudaGetSymbolAddress((void**)&q1h, g_Q1th); cudaGetSymbolAddress((void**)&q1l, g_Q1tl);
    cudaGetSymbolAddress((void**)&q2h, g_Q2th); cudaGetSymbolAddress((void**)&q2l, g_Q2tl);
    cudaGetSymbolAddress((void**)&x1f, g_X1f);  cudaGetSymbolAddress((void**)&x2f, g_X2f);
    cudaGetSymbolAddress((void**)&h1f, g_H1f);
    cudaGetSymbolAddress((void**)&h1p, g_H1p);  cudaGetSymbolAddress((void**)&h2p, g_H2p);
    cudaGetSymbolAddress((void**)&gt, g_GATE);

    const int SMEM = 2 * (3 * 128 * 64 * 2) + 1024;   // 99328 B
    cudaFuncSetAttribute(mma_gemm<0>, cudaFuncAttributeMaxDynamicSharedMemorySize, SMEM);
    cudaFuncSetAttribute(mma_gemm<1>, cudaFuncAttributeMaxDynamicSharedMemorySize, SMEM);

    // prep
    prep_saf<<<(M * 64 + 255) / 256, 256>>>(state, action, saf, M);
    prep_w1t<<<(1024 * 64 + 255) / 256, 256>>>(W1, w1h, w1l);
    prep_w2t<<<(1024 * 1024 + 255) / 256, 256>>>(W2, w2h, w2l);
    prep_wt<<<(256 * 1024 + 255) / 256, 256>>>(Wq1, q1h, q1l, 256, 1024);
    prep_wt<<<(128 * 256 + 255) / 256, 256>>>(Wq2, q2h, q2l, 128, 256);
    prep_gates<<<1, 64>>>(g1, g2, gt);

    const int MB = M / 128;

    // G0: [M,64pad] @ [1024,64]^T -> X1 (tanh * gate1)
    mma_gemm<0><<<dim3(8, MB), 256, SMEM>>>(saf, w1h, w1l, 64, 1024,
                                            b1, gt, nullptr, x1f);
    // G1: [M,1024] @ [1024,1024]^T -> X2 (tanh * gate2)   (dominant)
    mma_gemm<0><<<dim3(8, MB), 256, SMEM>>>(x1f, w2h, w2l, 1024, 1024,
                                            b2, gt + 32, nullptr, x2f);
    // G2: [M,1024] @ [256,1024]^T -> H1p (+bq1)
    mma_gemm<1><<<dim3(2, MB), 256, SMEM>>>(x2f, q1h, q1l, 1024, 256,
                                            bq1, nullptr, h1p, nullptr);
    ln_relu_f16<256><<<(M + 7) / 8, 256>>>(h1p, ln1g, ln1b, h1f, M);
    // G3: [M,256] @ [128,256]^T -> H2p (+bq2)
    mma_gemm<1><<<dim3(1, MB), 256, SMEM>>>(h1f, q2h, q2l, 256, 128,
                                            bq2, nullptr, h2p, nullptr);
    ln2_dot<<<(M + 7) / 8, 256>>>(h2p, ln2g, ln2b, Wq3, bq3, out, M);
}

// round 8
// speedup vs baseline: 8.1270x; 1.6094x over previous
#include <cuda_runtime.h>
#include <cuda_fp16.h>
#include <math.h>
#include <stdint.h>

// ===========================================================================
// COR_Critic — single-pass fp16 mma.sync (HMMA) + ldmatrix + cp.async.
// Both activations and weights rn-rounded to fp16; fp32 accumulate.
// Measured error budget: act-only rounding gave 2.3e-4; weight rounding adds
// an independent comparable term -> ~3.3e-4 total vs 1e-3 gate.
//   sa  = concat(state, action) -> [B,32] (padded to 64)
//   X1  = tanh(sa @ A1 + b1) * gate1      -> [B,1024]
//   X2  = tanh(X1 @ A2 + b2) * gate2      -> [B,1024]
//   H1p = X2 @ Wq1 + bq1 ; H1 = relu(LN(H1p))  (fp16)
//   H2p = H1 @ Wq2 + bq2 ; out = relu(LN(H2p)) @ Wq3 + bq3
// ===========================================================================

#define NB 131072
using fp16 = __half;

// ---------------- device scratch (static, no allocation) -------------------
__device__ fp16 g_SAf[(size_t)NB * 64];
__device__ fp16 g_W1t[1024 * 64];
__device__ fp16 g_W2t[1024 * 1024];
__device__ fp16 g_Q1t[256 * 1024];
__device__ fp16 g_Q2t[128 * 256];
__device__ fp16 g_X1f[(size_t)NB * 1024];
__device__ fp16 g_X2f[(size_t)NB * 1024];
__device__ float g_H1p[(size_t)NB * 256];
__device__ fp16 g_H1f[(size_t)NB * 256];
__device__ float g_H2p[(size_t)NB * 128];
__device__ float g_GATE[64];

// ---------------- PTX helpers ----------------------------------------------
__device__ __forceinline__ uint32_t smem_u32(const void* p) {
    uint32_t a;
    asm("{ .reg .u64 t; cvta.to.shared.u64 t, %1; cvt.u32.u64 %0, t; }"
        : "=r"(a) : "l"(p));
    return a;
}
__device__ __forceinline__ void cp16(uint32_t s, const void* g) {
    asm volatile("cp.async.cg.shared.global [%0], [%1], 16;" :: "r"(s), "l"(g));
}
#define CP_COMMIT() asm volatile("cp.async.commit_group;" ::: "memory")
__device__ __forceinline__ void ldsm4(uint32_t* r, uint32_t a) {
    asm volatile("ldmatrix.sync.aligned.m8n8.x4.shared.b16 {%0,%1,%2,%3}, [%4];"
                 : "=r"(r[0]), "=r"(r[1]), "=r"(r[2]), "=r"(r[3]) : "r"(a));
}
__device__ __forceinline__ void ldsm2(uint32_t* r, uint32_t a) {
    asm volatile("ldmatrix.sync.aligned.m8n8.x2.shared.b16 {%0,%1}, [%2];"
                 : "=r"(r[0]), "=r"(r[1]) : "r"(a));
}
__device__ __forceinline__ void mma16816(float* d, const uint32_t* a, const uint32_t* b) {
    asm volatile(
        "mma.sync.aligned.m16n8k16.row.col.f32.f16.f16.f32 "
        "{%0,%1,%2,%3}, {%4,%5,%6,%7}, {%8,%9}, {%0,%1,%2,%3};"
        : "+f"(d[0]), "+f"(d[1]), "+f"(d[2]), "+f"(d[3])
        : "r"(a[0]), "r"(a[1]), "r"(a[2]), "r"(a[3]), "r"(b[0]), "r"(b[1]));
}

// ---------------- prep kernels ---------------------------------------------
__global__ void prep_saf(const float* __restrict__ st, const float* __restrict__ ac,
                         fp16* __restrict__ o, int M) {
    int idx = blockIdx.x * blockDim.x + threadIdx.x;
    if (idx >= M * 64) return;
    int b = idx >> 6, j = idx & 63;
    float v = 0.f;
    if (j < 24) v = st[b * 24 + j];
    else if (j < 32) v = ac[b * 8 + (j - 24)];
    o[idx] = __float2half_rn(v);
}
// A1t[n,k] = W1[n>>5, k, n&31], k<32 else 0
__global__ void prep_w1t(const float* __restrict__ W, fp16* __restrict__ h) {
    int idx = blockIdx.x * blockDim.x + threadIdx.x;
    if (idx >= 1024 * 64) return;
    int n = idx >> 6, k = idx & 63;
    float v = (k < 32) ? W[((size_t)((n >> 5) * 32 + k)) * 32 + (n & 31)] : 0.f;
    h[idx] = __float2half_rn(v);
}
// A2t[n,k] = W2[n>>5, k, n&31]
__global__ void prep_w2t(const float* __restrict__ W, fp16* __restrict__ h) {
    int idx = blockIdx.x * blockDim.x + threadIdx.x;
    if (idx >= 1024 * 1024) return;
    int n = idx >> 10, k = idx & 1023;
    h[idx] = __float2half_rn(W[((size_t)(n >> 5) * 1024 + k) * 32 + (n & 31)]);
}
// Qt[n,k] = Wq[k*N + n]
__global__ void prep_wt(const float* __restrict__ W, fp16* __restrict__ h, int Nn, int K) {
    int idx = blockIdx.x * blockDim.x + threadIdx.x;
    if (idx >= Nn * K) return;
    int n = idx / K, k = idx - n * K;
    h[idx] = __float2half_rn(W[(size_t)k * Nn + n]);
}
__global__ void prep_gates(const float* __restrict__ g1, const float* __restrict__ g2,
                           float* __restrict__ out) {
    int t = threadIdx.x;
    if (t < 32)      out[t] = 1.0f / (1.0f + expf(-g1[t]));
    else if (t < 64) out[t] = 1.0f / (1.0f + expf(-g2[t - 32]));
}

// ---------------- HMMA GEMM -------------------------------------------------
// C[M,N] = Af[M,K] @ W[N,K]^T, fp32 acc in regs.
// BM=128, BN=128, BK=64, 8 warps (4m x 2n), warp tile 32x64.
// EPI 0: tanh(acc+bias)*gate -> Cfp16.   EPI 1: acc+bias -> Cf fp32.
template <int EPI>
__global__ void __launch_bounds__(256)
mma_gemm(const fp16* __restrict__ Af, const fp16* __restrict__ Bw,
         int K, int ldC,
         const float* __restrict__ bias, const float* __restrict__ gate,
         float* __restrict__ Cf, fp16* __restrict__ Ch) {
    constexpr int TILE = 128 * 64 * 2;   // 16 KB per operand tile
    constexpr int BUF = 2 * TILE;        // Af | Bw

    extern __shared__ char dsm[];
    const uint32_t sb = (smem_u32(dsm) + 1023) & ~1023u;

    const int tid = threadIdx.x;
    const int wid = tid >> 5, lane = tid & 31;
    const int wm = wid >> 1, wn = wid & 1;
    const size_t bm = (size_t)blockIdx.y * 128;
    const int bn = blockIdx.x * 128;
    const int nk = K >> 6;

    auto load_tile = [&](int kt, int buf) {
        const uint32_t base = sb + buf * BUF;
#pragma unroll
        for (int i = 0; i < 4; i++) {
            const int c = tid + 256 * i;           // 0..1023
            const int row = c >> 3;
            const int cb = (c & 7) << 4;
            const uint32_t sw = (uint32_t)(row * 128) + (uint32_t)(cb ^ ((row & 7) << 4));
            const size_t kofs = (size_t)kt * 64 + ((c & 7) << 3);
            cp16(base + sw, Af + (bm + row) * (size_t)K + kofs);
            cp16(base + TILE + sw, Bw + (size_t)(bn + row) * K + kofs);
        }
    };

    // per-thread ldmatrix address components
    const int r15 = lane & 15, halfA = lane >> 4;
    int pA[2], xA[2];
#pragma unroll
    for (int mt = 0; mt < 2; mt++) {
        const int rowA = wm * 32 + mt * 16 + r15;
        pA[mt] = rowA * 128;
        xA[mt] = (rowA & 7) << 4;
    }
    const int l4 = lane & 15;
    const int l8 = l4 & 7, halfB = l4 >> 3;
    const int xB = l8 << 4;
    int pB[8];
#pragma unroll
    for (int nt = 0; nt < 8; nt++) pB[nt] = (wn * 64 + nt * 8 + l8) * 128;

    float acc[2][8][4];
#pragma unroll
    for (int mt = 0; mt < 2; mt++)
#pragma unroll
        for (int nt = 0; nt < 8; nt++)
#pragma unroll
            for (int q = 0; q < 4; q++) acc[mt][nt][q] = 0.f;

    load_tile(0, 0);
    CP_COMMIT();

    for (int kt = 0; kt < nk; kt++) {
        const int buf = kt & 1;
        if (kt + 1 < nk) {
            load_tile(kt + 1, buf ^ 1);
            CP_COMMIT();
            asm volatile("cp.async.wait_group 1;" ::: "memory");
        } else {
            asm volatile("cp.async.wait_group 0;" ::: "memory");
        }
        __syncthreads();

        const uint32_t tA = sb + buf * BUF;
        const uint32_t tB = tA + TILE;

#pragma unroll
        for (int ks = 0; ks < 4; ks++) {
            const int kbA = ks * 32 + 16 * halfA;
            const int kbB = ks * 32 + 16 * halfB;
            uint32_t a[2][4], bfr[8][2];
#pragma unroll
            for (int mt = 0; mt < 2; mt++)
                ldsm4(a[mt], tA + pA[mt] + (kbA ^ xA[mt]));
#pragma unroll
            for (int nt = 0; nt < 8; nt++)
                ldsm2(bfr[nt], tB + pB[nt] + (kbB ^ xB));
#pragma unroll
            for (int mt = 0; mt < 2; mt++)
#pragma unroll
                for (int nt = 0; nt < 8; nt++)
                    mma16816(acc[mt][nt], a[mt], bfr[nt]);
        }
        __syncthreads();
    }

    // ---- epilogue (acc in regs) ----
    const int gid = lane >> 2, qd = lane & 3;
#pragma unroll
    for (int nt = 0; nt < 8; nt++) {
        const int c = bn + wn * 64 + nt * 8 + qd * 2;
        const float b0 = bias[c], b1 = bias[c + 1];
        float gv = 0.f;
        if (EPI == 0) gv = gate[c >> 5];
#pragma unroll
        for (int mt = 0; mt < 2; mt++) {
            const size_t r0 = bm + wm * 32 + mt * 16 + gid;
            if (EPI == 0) {
#pragma unroll
                for (int half = 0; half < 2; half++) {
                    const size_t row = r0 + 8 * half;
                    const float v0 = tanhf(acc[mt][nt][2 * half + 0] + b0) * gv;
                    const float v1 = tanhf(acc[mt][nt][2 * half + 1] + b1) * gv;
                    const fp16 h0 = __float2half_rn(v0);
                    const fp16 h1 = __float2half_rn(v1);
                    *(uint32_t*)(Ch + row * (size_t)ldC + c) =
                        ((uint32_t)__half_as_ushort(h1) << 16) | __half_as_ushort(h0);
                }
            } else {
#pragma unroll
                for (int half = 0; half < 2; half++) {
                    const size_t row = r0 + 8 * half;
                    float2 o;
                    o.x = acc[mt][nt][2 * half + 0] + b0;
                    o.y = acc[mt][nt][2 * half + 1] + b1;
                    *(float2*)(Cf + row * (size_t)ldC + c) = o;
                }
            }
        }
    }
}

// ---------------- LN + ReLU -> fp16 (one warp per row) ---------------------
template <int D>
__global__ void ln_relu_f16(const float* __restrict__ X, const float* __restrict__ gm,
                            const float* __restrict__ bt, fp16* __restrict__ Y, int M) {
    const int row = blockIdx.x * (blockDim.x >> 5) + (threadIdx.x >> 5);
    if (row >= M) return;
    const int lane = threadIdx.x & 31;
    constexpr int PT = D / 32;
    float v[PT];
    const float* rp = X + (size_t)row * D;
    float s = 0.f;
#pragma unroll
    for (int i = 0; i < PT; i++) { v[i] = rp[lane + 32 * i]; s += v[i]; }
#pragma unroll
    for (int o = 16; o; o >>= 1) s += __shfl_xor_sync(0xffffffffu, s, o);
    const float mu = s * (1.0f / D);
    float vs = 0.f;
#pragma unroll
    for (int i = 0; i < PT; i++) { float d = v[i] - mu; vs += d * d; }
#pragma unroll
    for (int o = 16; o; o >>= 1) vs += __shfl_xor_sync(0xffffffffu, vs, o);
    const float inv = rsqrtf(vs * (1.0f / D) + 1e-5f);
#pragma unroll
    for (int i = 0; i < PT; i++) {
        float y = (v[i] - mu) * inv * gm[lane + 32 * i] + bt[lane + 32 * i];
        Y[(size_t)row * D + lane + 32 * i] = __float2half_rn(fmaxf(y, 0.f));
    }
}

// ---------------- fused LN2 + ReLU + dot (one warp per row) ----------------
__global__ void ln2_dot(const float* __restrict__ X, const float* __restrict__ gm,
                        const float* __restrict__ bt, const float* __restrict__ w,
                        const float* __restrict__ b, float* __restrict__ out, int M) {
    const int row = blockIdx.x * (blockDim.x >> 5) + (threadIdx.x >> 5);
    if (row >= M) return;
    const int lane = threadIdx.x & 31;
    float v[4];
    const float* rp = X + (size_t)row * 128;
    float s = 0.f;
#pragma unroll
    for (int i = 0; i < 4; i++) { v[i] = rp[lane + 32 * i]; s += v[i]; }
#pragma unroll
    for (int o = 16; o; o >>= 1) s += __shfl_xor_sync(0xffffffffu, s, o);
    const float mu = s * (1.0f / 128.0f);
    float vs = 0.f;
#pragma unroll
    for (int i = 0; i < 4; i++) { float d = v[i] - mu; vs += d * d; }
#pragma unroll
    for (int o = 16; o; o >>= 1) vs += __shfl_xor_sync(0xffffffffu, vs, o);
    const float inv = rsqrtf(vs * (1.0f / 128.0f) + 1e-5f);
    float acc = 0.f;
#pragma unroll
    for (int i = 0; i < 4; i++) {
        float y = (v[i] - mu) * inv * gm[lane + 32 * i] + bt[lane + 32 * i];
        y = fmaxf(y, 0.f);
        acc = fmaf(y, w[lane + 32 * i], acc);
    }
#pragma unroll
    for (int o = 16; o; o >>= 1) acc += __shfl_xor_sync(0xffffffffu, acc, o);
    if (lane == 0) out[row] = acc + b[0];
}

// ---------------- launch ----------------------------------------------------
extern "C" void kernel_launch(void* const* d_in, const int* in_sizes, int n_in,
                              void* d_out, int out_size) {
    const float* state = (const float*)d_in[0];
    const float* action = (const float*)d_in[1];
    const float* W1 = (const float*)d_in[2];
    const float* b1 = (const float*)d_in[3];
    const float* g1 = (const float*)d_in[4];
    const float* W2 = (const float*)d_in[5];
    const float* b2 = (const float*)d_in[6];
    const float* g2 = (const float*)d_in[7];
    const float* Wq1 = (const float*)d_in[8];
    const float* bq1 = (const float*)d_in[9];
    const float* ln1g = (const float*)d_in[10];
    const float* ln1b = (const float*)d_in[11];
    const float* Wq2 = (const float*)d_in[12];
    const float* bq2 = (const float*)d_in[13];
    const float* ln2g = (const float*)d_in[14];
    const float* ln2b = (const float*)d_in[15];
    const float* Wq3 = (const float*)d_in[16];
    const float* bq3 = (const float*)d_in[17];
    float* out = (float*)d_out;

    const int M = in_sizes[0] / 24;
    if (M <= 0) return;

    fp16 *saf, *w1t, *w2t, *q1t, *q2t, *x1f, *x2f, *h1f;
    float *h1p, *h2p, *gt;
    cudaGetSymbolAddress((void**)&saf, g_SAf);
    cudaGetSymbolAddress((void**)&w1t, g_W1t);
    cudaGetSymbolAddress((void**)&w2t, g_W2t);
    cudaGetSymbolAddress((void**)&q1t, g_Q1t);
    cudaGetSymbolAddress((void**)&q2t, g_Q2t);
    cudaGetSymbolAddress((void**)&x1f, g_X1f);
    cudaGetSymbolAddress((void**)&x2f, g_X2f);
    cudaGetSymbolAddress((void**)&h1f, g_H1f);
    cudaGetSymbolAddress((void**)&h1p, g_H1p);
    cudaGetSymbolAddress((void**)&h2p, g_H2p);
    cudaGetSymbolAddress((void**)&gt, g_GATE);

    const int SMEM = 2 * (2 * 128 * 64 * 2) + 1024;   // 66560 B
    cudaFuncSetAttribute(mma_gemm<0>, cudaFuncAttributeMaxDynamicSharedMemorySize, SMEM);
    cudaFuncSetAttribute(mma_gemm<1>, cudaFuncAttributeMaxDynamicSharedMemorySize, SMEM);

    // prep
    prep_saf<<<(M * 64 + 255) / 256, 256>>>(state, action, saf, M);
    prep_w1t<<<(1024 * 64 + 255) / 256, 256>>>(W1, w1t);
    prep_w2t<<<(1024 * 1024 + 255) / 256, 256>>>(W2, w2t);
    prep_wt<<<(256 * 1024 + 255) / 256, 256>>>(Wq1, q1t, 256, 1024);
    prep_wt<<<(128 * 256 + 255) / 256, 256>>>(Wq2, q2t, 128, 256);
    prep_gates<<<1, 64>>>(g1, g2, gt);

    const int MB = M / 128;

    // G0: [M,64pad] @ [1024,64]^T -> X1 (tanh * gate1)
    mma_gemm<0><<<dim3(8, MB), 256, SMEM>>>(saf, w1t, 64, 1024, b1, gt, nullptr, x1f);
    // G1: [M,1024] @ [1024,1024]^T -> X2 (tanh * gate2)   (dominant)
    mma_gemm<0><<<dim3(8, MB), 256, SMEM>>>(x1f, w2t, 1024, 1024, b2, gt + 32, nullptr, x2f);
    // G2: [M,1024] @ [256,1024]^T -> H1p (+bq1)
    mma_gemm<1><<<dim3(2, MB), 256, SMEM>>>(x2f, q1t, 1024, 256, bq1, nullptr, h1p, nullptr);
    ln_relu_f16<256><<<(M + 7) / 8, 256>>>(h1p, ln1g, ln1b, h1f, M);
    // G3: [M,256] @ [128,256]^T -> H2p (+bq2)
    mma_gemm<1><<<dim3(1, MB), 256, SMEM>>>(h1f, q2t, 256, 128, bq2, nullptr, h2p, nullptr);
    ln2_dot<<<(M + 7) / 8, 256>>>(h2p, ln2g, ln2b, Wq3, bq3, out, M);
}